// round 14
// baseline (speedup 1.0000x reference)
#include <cuda_runtime.h>

#define BS    2048
#define NINP  512
#define NHID  512
#define TT    8
#define MM    32
#define NTOT  32768
#define GI_COLS 768
#define KSPLIT 4
#define FT    224              // fused kernel threads; grid 147 ~= #SMs

typedef unsigned long long u64;
typedef unsigned int u32;

// device scratch
__device__ float g_gi[BS * GI_COLS];            // 6 MB
__device__ float g_gip[KSPLIT][BS * GI_COLS];   // gemm partials, 25 MB

// ---- packed f32x2 helpers --------------------------------------------------
__device__ __forceinline__ void fma2(u64& acc, u64 a, u64 b) {
    asm("fma.rn.f32x2 %0, %1, %2, %0;" : "+l"(acc) : "l"(a), "l"(b));
}
__device__ __forceinline__ u64 pk(float lo, float hi) {
    u64 r; asm("mov.b64 %0, {%1, %2};" : "=l"(r) : "f"(lo), "f"(hi)); return r;
}
__device__ __forceinline__ void unpk(float& lo, float& hi, u64 v) {
    asm("mov.b64 {%0, %1}, %2;" : "=f"(lo), "=f"(hi) : "l"(v));
}
__device__ __forceinline__ float hadd(u64 v) {
    float a, b; unpk(a, b, v); return a + b;
}

// ---------------------------------------------------------------------------
// Kernel 1: gi partials = x @ W_ih^T (k-split by 4). FFMA2, 128x64 tile.
// (verified round-11 structure, unchanged)
// ---------------------------------------------------------------------------
#define SA 132
#define SB 68
#define GEMM_SMEM ((2 * 32 * SA + 2 * 32 * SB) * 4)   // 51200 B

__global__ void __launch_bounds__(128, 3) gemm_gi_kernel(
    const float* __restrict__ A,
    const float* __restrict__ B)
{
    extern __shared__ float smem[];
    float* Asm = smem;
    float* Bsm = smem + 2 * 32 * SA;

    const int tid = threadIdx.x;
    const int tx  = tid & 7;
    const int ty  = tid >> 3;
    const int n0  = blockIdx.x * 64;
    const int m0  = blockIdx.y * 128;
    const int ks  = blockIdx.z;
    const int kb0 = ks * 128;

    float4 ra[8], rb[4];

    #define LDG_CHUNK(c) {                                                    \
        const int kb_ = kb0 + (c) * 32;                                       \
        _Pragma("unroll")                                                     \
        for (int i_ = 0; i_ < 8; i_++) {                                      \
            int idx_ = tid + 128 * i_;                                        \
            ra[i_] = *(const float4*)&A[(m0 + (idx_ >> 3)) * NINP + kb_ + (idx_ & 7) * 4]; \
        }                                                                     \
        _Pragma("unroll")                                                     \
        for (int i_ = 0; i_ < 4; i_++) {                                      \
            int idx_ = tid + 128 * i_;                                        \
            rb[i_] = *(const float4*)&B[(n0 + (idx_ >> 3)) * NINP + kb_ + (idx_ & 7) * 4]; \
        }                                                                     \
    }

    #define STS_CHUNK(buf) {                                                  \
        _Pragma("unroll")                                                     \
        for (int i_ = 0; i_ < 8; i_++) {                                      \
            int idx_ = tid + 128 * i_;                                        \
            int r_ = idx_ >> 3, kc_ = (idx_ & 7) * 4;                         \
            Asm[(buf) * 32 * SA + (kc_ + 0) * SA + r_] = ra[i_].x;            \
            Asm[(buf) * 32 * SA + (kc_ + 1) * SA + r_] = ra[i_].y;            \
            Asm[(buf) * 32 * SA + (kc_ + 2) * SA + r_] = ra[i_].z;            \
            Asm[(buf) * 32 * SA + (kc_ + 3) * SA + r_] = ra[i_].w;            \
        }                                                                     \
        _Pragma("unroll")                                                     \
        for (int i_ = 0; i_ < 4; i_++) {                                      \
            int idx_ = tid + 128 * i_;                                        \
            int r_ = idx_ >> 3, kc_ = (idx_ & 7) * 4;                         \
            Bsm[(buf) * 32 * SB + (kc_ + 0) * SB + r_] = rb[i_].x;            \
            Bsm[(buf) * 32 * SB + (kc_ + 1) * SB + r_] = rb[i_].y;            \
            Bsm[(buf) * 32 * SB + (kc_ + 2) * SB + r_] = rb[i_].z;            \
            Bsm[(buf) * 32 * SB + (kc_ + 3) * SB + r_] = rb[i_].w;            \
        }                                                                     \
    }

    u64 acc[4][8];
#pragma unroll
    for (int i = 0; i < 4; i++)
#pragma unroll
        for (int j = 0; j < 8; j++) acc[i][j] = 0ull;

    LDG_CHUNK(0);
    STS_CHUNK(0);
    LDG_CHUNK(1);
    __syncthreads();

#pragma unroll 1
    for (int c = 0; c < 4; c++) {
        const int buf = c & 1;
        if (c < 3) STS_CHUNK(buf ^ 1);
        if (c < 2) LDG_CHUNK(c + 2);

        const float* Ab = Asm + buf * 32 * SA;
        const float* Bb = Bsm + buf * 32 * SB;
#pragma unroll
        for (int k = 0; k < 32; k++) {
            ulonglong2 a1 = *(const ulonglong2*)(Ab + k * SA + ty * 4);
            ulonglong2 a2 = *(const ulonglong2*)(Ab + k * SA + 64 + ty * 4);
            float4 b1 = *(const float4*)(Bb + k * SB + tx * 4);
            float4 b2 = *(const float4*)(Bb + k * SB + 32 + tx * 4);
            u64 bb[8];
            bb[0] = pk(b1.x, b1.x); bb[1] = pk(b1.y, b1.y);
            bb[2] = pk(b1.z, b1.z); bb[3] = pk(b1.w, b1.w);
            bb[4] = pk(b2.x, b2.x); bb[5] = pk(b2.y, b2.y);
            bb[6] = pk(b2.z, b2.z); bb[7] = pk(b2.w, b2.w);
#pragma unroll
            for (int j = 0; j < 8; j++) {
                fma2(acc[0][j], a1.x, bb[j]);
                fma2(acc[1][j], a1.y, bb[j]);
                fma2(acc[2][j], a2.x, bb[j]);
                fma2(acc[3][j], a2.y, bb[j]);
            }
        }
        __syncthreads();
    }

    float* gp = g_gip[ks];
#pragma unroll
    for (int mp = 0; mp < 4; mp++) {
        int mrow = m0 + ((mp < 2) ? (ty * 4 + mp * 2) : (64 + ty * 4 + (mp - 2) * 2));
        float lo[8], hi[8];
#pragma unroll
        for (int j = 0; j < 8; j++) unpk(lo[j], hi[j], acc[mp][j]);
        *(float4*)&gp[mrow * GI_COLS + n0 + tx * 4] =
            make_float4(lo[0], lo[1], lo[2], lo[3]);
        *(float4*)&gp[mrow * GI_COLS + n0 + 32 + tx * 4] =
            make_float4(lo[4], lo[5], lo[6], lo[7]);
        *(float4*)&gp[(mrow + 1) * GI_COLS + n0 + tx * 4] =
            make_float4(hi[0], hi[1], hi[2], hi[3]);
        *(float4*)&gp[(mrow + 1) * GI_COLS + n0 + 32 + tx * 4] =
            make_float4(hi[4], hi[5], hi[6], hi[7]);
    }
    #undef LDG_CHUNK
    #undef STS_CHUNK
}

// ---------------------------------------------------------------------------
// Kernel 1b: reduce partials + bias -> g_gi (unchanged)
// ---------------------------------------------------------------------------
__global__ void __launch_bounds__(256) reduce_gi_kernel(
    const float* __restrict__ bias)
{
    int i = blockIdx.x * 256 + threadIdx.x;
    int col = (i * 4) % GI_COLS;
    float4 b = *(const float4*)&bias[col];
    float4 s0 = *(const float4*)&g_gip[0][i * 4];
    float4 s1 = *(const float4*)&g_gip[1][i * 4];
    float4 s2 = *(const float4*)&g_gip[2][i * 4];
    float4 s3 = *(const float4*)&g_gip[3][i * 4];
    float4 r;
    r.x = ((s0.x + s1.x) + (s2.x + s3.x)) + b.x;
    r.y = ((s0.y + s1.y) + (s2.y + s3.y)) + b.y;
    r.z = ((s0.z + s1.z) + (s2.z + s3.z)) + b.z;
    r.w = ((s0.w + s1.w) + (s2.w + s3.w)) + b.w;
    *(float4*)&g_gi[i * 4] = r;
}

// ---------------------------------------------------------------------------
// Kernel 2: FUSED gates + attention + gumbel select + outputs.
// Thread-per-n, all 8 templates in-thread. Packed-h FFMA2 gate math
// (verified r12 inner loop). Online argmax; pass-2 recompute of the selected
// template (no hnext storage anywhere). 224 thr, 1 block/SM, 117 KB smem.
// ---------------------------------------------------------------------------
#define SMEM_FLOATS (TT*96*MM + TT*MM*16 + MM*16 + TT*96)   // 29952
#define FUSED_SMEM  (SMEM_FLOATS * 4)                        // 119808

__global__ void __launch_bounds__(FT, 1) fused_kernel(
    const float* __restrict__ h,
    const float* __restrict__ W_hh,
    const float* __restrict__ b_hh,
    const float* __restrict__ w_read,
    const float* __restrict__ w_write,
    const float* __restrict__ gum,
    float* __restrict__ out)
{
    extern __shared__ float sm[];
    float* Wg = sm;                      // W_hh [t][96][32]   24576
    float* Ww = Wg + TT*96*MM;           // w_write [t][32][16] 4096
    float* Wr = Ww + TT*MM*16;           // w_read [32][16]      512
    float* bh = Wr + MM*16;              // b_hh [t][96]         768
    const int tid = threadIdx.x;

    {   // stage weights (contiguous float4 copies)
        float4* d = (float4*)Wg; const float4* s = (const float4*)W_hh;
        for (int i = tid; i < TT*96*MM/4; i += FT) d[i] = s[i];
        d = (float4*)Ww; s = (const float4*)w_write;
        for (int i = tid; i < TT*MM*16/4; i += FT) d[i] = s[i];
        d = (float4*)Wr; s = (const float4*)w_read;
        for (int i = tid; i < MM*16/4; i += FT) d[i] = s[i];
        d = (float4*)bh; s = (const float4*)b_hh;
        for (int i = tid; i < TT*96/4; i += FT) d[i] = s[i];
    }
    __syncthreads();

    const int n = blockIdx.x * FT + tid;
    if (n >= NTOT) return;               // no later block syncs
    const int b = n >> 4;

    // h state: packed m-pairs (32 regs), scalars unpacked on demand
    u64 hp2[16];
    {
        const ulonglong2* h1 = (const ulonglong2*)(h + n * MM);
#pragma unroll
        for (int q = 0; q < 8; q++) {
            ulonglong2 v = h1[q]; hp2[2*q] = v.x; hp2[2*q+1] = v.y;
        }
    }

    // h_read[f] = sum_m h[m]*w_read[m][f]; then pack into f-pairs
    u64 hrp[8];
    {
        float hr[16];
#pragma unroll
        for (int f = 0; f < 16; f++) hr[f] = 0.f;
#pragma unroll 4
        for (int m = 0; m < 32; m++) {
            const float4* w = (const float4*)(Wr + m * 16);
            float lo, hi; unpk(lo, hi, hp2[m >> 1]);
            float hm = (m & 1) ? hi : lo;
#pragma unroll
            for (int f4 = 0; f4 < 4; f4++) {
                float4 v = w[f4];
                hr[4*f4]   = fmaf(hm, v.x, hr[4*f4]);
                hr[4*f4+1] = fmaf(hm, v.y, hr[4*f4+1]);
                hr[4*f4+2] = fmaf(hm, v.z, hr[4*f4+2]);
                hr[4*f4+3] = fmaf(hm, v.w, hr[4*f4+3]);
            }
        }
#pragma unroll
        for (int f2 = 0; f2 < 8; f2++) hrp[f2] = pk(hr[2*f2], hr[2*f2+1]);
    }

    // gumbel noise prefetch
    float g8[8];
    {
        const float4* gp = (const float4*)(gum + n * TT);
        float4 a = gp[0], c = gp[1];
        g8[0]=a.x; g8[1]=a.y; g8[2]=a.z; g8[3]=a.w;
        g8[4]=c.x; g8[5]=c.y; g8[6]=c.z; g8[7]=c.w;
    }

    float rmax = -1e30f, rsum = 0.f;
    int amax = 0;

    // ---- pass 1: logits via online softmax/argmax (no hnext storage) ----
#pragma unroll 1
    for (int t = 0; t < TT; t++) {
        const float* gib = g_gi + b * GI_COLS + t * 96;
        const float* wt  = Wg + t * 96 * MM;
        const float* wwt = Ww + t * MM * 16;
        const float* bht = bh + t * 96;
        float lg = 0.f;

#pragma unroll 2
        for (int l4 = 0; l4 < 8; l4++) {
            float Ga[4], Gb[4], Gc[4];
            *(float4*)Ga = *(const float4*)(gib + 4*l4);
            *(float4*)Gb = *(const float4*)(gib + 32 + 4*l4);
            *(float4*)Gc = *(const float4*)(gib + 64 + 4*l4);
#pragma unroll
            for (int li = 0; li < 4; li++) {
                const int l = 4*l4 + li;
                const ulonglong2* wr = (const ulonglong2*)(wt + l * 32);
                const ulonglong2* wz = (const ulonglong2*)(wt + (32 + l) * 32);
                const ulonglong2* wn = (const ulonglong2*)(wt + (64 + l) * 32);
                u64 aR = pk(bht[l],      0.f);
                u64 aZ = pk(bht[32 + l], 0.f);
                u64 aN = pk(bht[64 + l], 0.f);
#pragma unroll
                for (int q = 0; q < 8; q++) {
                    ulonglong2 wa = wr[q];
                    fma2(aR, wa.x, hp2[2*q]); fma2(aR, wa.y, hp2[2*q+1]);
                }
#pragma unroll
                for (int q = 0; q < 8; q++) {
                    ulonglong2 wb = wz[q];
                    fma2(aZ, wb.x, hp2[2*q]); fma2(aZ, wb.y, hp2[2*q+1]);
                }
#pragma unroll
                for (int q = 0; q < 8; q++) {
                    ulonglong2 wc = wn[q];
                    fma2(aN, wc.x, hp2[2*q]); fma2(aN, wc.y, hp2[2*q+1]);
                }
                // av = w_write[t][l] . h_read (packed f-pairs)
                const ulonglong2* ww = (const ulonglong2*)(wwt + l * 16);
                ulonglong2 w0 = ww[0], w1 = ww[1];
                u64 aA = 0ull;
                fma2(aA, w0.x, hrp[0]); fma2(aA, w0.y, hrp[1]);
                fma2(aA, w1.x, hrp[2]); fma2(aA, w1.y, hrp[3]);
                ulonglong2 w2 = ((const ulonglong2*)(wwt + l * 16))[2];
                ulonglong2 w3 = ((const ulonglong2*)(wwt + l * 16))[3];
                fma2(aA, w2.x, hrp[4]); fma2(aA, w2.y, hrp[5]);
                fma2(aA, w3.x, hrp[6]); fma2(aA, w3.y, hrp[7]);

                float ar = hadd(aR), az = hadd(aZ), an = hadd(aN), av = hadd(aA);
                float lo, hi; unpk(lo, hi, hp2[l >> 1]);
                float hl = (l & 1) ? hi : lo;
                float r  = __fdividef(1.f, 1.f + __expf(-(Ga[li] + ar)));
                float z  = __fdividef(1.f, 1.f + __expf(-(Gb[li] + az)));
                float xn = Gc[li] + r * an;
                float e2 = __expf(-2.f * xn);
                float nn = __fdividef(1.f - e2, 1.f + e2);   // tanh
                float hn = (1.f - z) * nn + z * hl;
                lg = fmaf(hn, av, lg);
            }
        }
        float s = (lg + g8[t]) * 2.0f;      // /TAU, TAU=0.5
        if (s > rmax) {
            rsum = rsum * __expf(rmax - s) + 1.f;
            rmax = s; amax = t;
        } else {
            rsum += __expf(s - rmax);
        }
    }

    float p = __fdividef(1.f, rsum);        // softmax value at argmax
    float attv = (1.f + p) - p;             // straight-through residual, exact

    // ---- pass 2: recompute hnext for the selected template, write out ----
    {
        const float* gib = g_gi + b * GI_COLS + amax * 96;
        const float* wt  = Wg + amax * 96 * MM;
        const float* bht = bh + amax * 96;
        float4* ho = (float4*)(out + n * MM);

#pragma unroll 2
        for (int l4 = 0; l4 < 8; l4++) {
            float Ga[4], Gb[4], Gc[4];
            *(float4*)Ga = *(const float4*)(gib + 4*l4);
            *(float4*)Gb = *(const float4*)(gib + 32 + 4*l4);
            *(float4*)Gc = *(const float4*)(gib + 64 + 4*l4);
            float o4[4];
#pragma unroll
            for (int li = 0; li < 4; li++) {
                const int l = 4*l4 + li;
                const ulonglong2* wr = (const ulonglong2*)(wt + l * 32);
                const ulonglong2* wz = (const ulonglong2*)(wt + (32 + l) * 32);
                const ulonglong2* wn = (const ulonglong2*)(wt + (64 + l) * 32);
                u64 aR = pk(bht[l],      0.f);
                u64 aZ = pk(bht[32 + l], 0.f);
                u64 aN = pk(bht[64 + l], 0.f);
#pragma unroll
                for (int q = 0; q < 8; q++) {
                    ulonglong2 wa = wr[q];
                    fma2(aR, wa.x, hp2[2*q]); fma2(aR, wa.y, hp2[2*q+1]);
                }
#pragma unroll
                for (int q = 0; q < 8; q++) {
                    ulonglong2 wb = wz[q];
                    fma2(aZ, wb.x, hp2[2*q]); fma2(aZ, wb.y, hp2[2*q+1]);
                }
#pragma unroll
                for (int q = 0; q < 8; q++) {
                    ulonglong2 wc = wn[q];
                    fma2(aN, wc.x, hp2[2*q]); fma2(aN, wc.y, hp2[2*q+1]);
                }
                float ar = hadd(aR), az = hadd(aZ), an = hadd(aN);
                float lo, hi; unpk(lo, hi, hp2[l >> 1]);
                float hl = (l & 1) ? hi : lo;
                float r  = __fdividef(1.f, 1.f + __expf(-(Ga[li] + ar)));
                float z  = __fdividef(1.f, 1.f + __expf(-(Gb[li] + az)));
                float xn = Gc[li] + r * an;
                float e2 = __expf(-2.f * xn);
                float nn = __fdividef(1.f - e2, 1.f + e2);
                float hn = (1.f - z) * nn + z * hl;
                o4[li] = attv * hn;
            }
            ho[l4] = *(float4*)o4;
        }
    }

    float* ao = out + BS * NHID + n * TT;
#pragma unroll
    for (int t = 0; t < TT; t++) ao[t] = (t == amax) ? attv : 0.f;
}

// ---------------------------------------------------------------------------
extern "C" void kernel_launch(void* const* d_in, const int* in_sizes, int n_in,
                              void* d_out, int out_size)
{
    const float* x       = (const float*)d_in[0];
    const float* h       = (const float*)d_in[1];
    const float* W_ih    = (const float*)d_in[2];
    const float* W_hh    = (const float*)d_in[3];
    const float* b_ih    = (const float*)d_in[4];
    const float* b_hh    = (const float*)d_in[5];
    const float* w_read  = (const float*)d_in[6];
    const float* w_write = (const float*)d_in[7];
    const float* gum     = (const float*)d_in[8];
    float* out = (float*)d_out;

    // gi GEMM: k-split x4, fma2, then reduce(+bias)
    cudaFuncSetAttribute(gemm_gi_kernel,
                         cudaFuncAttributeMaxDynamicSharedMemorySize, GEMM_SMEM);
    dim3 g1(GI_COLS / 64, BS / 128, KSPLIT);          // (12, 16, 4) = 768
    gemm_gi_kernel<<<g1, 128, GEMM_SMEM>>>(x, W_ih);
    reduce_gi_kernel<<<BS * GI_COLS / 4 / 256, 256>>>(b_ih);

    // fused gates + attention + select + outputs
    cudaFuncSetAttribute(fused_kernel,
                         cudaFuncAttributeMaxDynamicSharedMemorySize, FUSED_SMEM);
    fused_kernel<<<(NTOT + FT - 1) / FT, FT, FUSED_SMEM>>>(
        h, W_hh, b_hh, w_read, w_write, gum, out);
}

// round 15
// speedup vs baseline: 1.4361x; 1.4361x over previous
#include <cuda_runtime.h>

#define BS    2048
#define NINP  512
#define NHID  512
#define TT    8
#define MM    32
#define NTOT  32768
#define GI_COLS 768
#define NPAIR (NTOT/2)   // 16384

typedef unsigned long long u64;
typedef unsigned int u32;

// device scratch
__device__ float g_gi[BS * GI_COLS];            // 6 MB
__device__ float g_hn[TT * NTOT * MM];          // hnext, 32 MB
__device__ float g_lg[NTOT * TT];               // logits, 1 MB
__device__ float g_hr[NTOT * 16];               // h_read, 2 MB

// ---- packed f32x2 helpers --------------------------------------------------
__device__ __forceinline__ void fma2(u64& acc, u64 a, u64 b) {
    asm("fma.rn.f32x2 %0, %1, %2, %0;" : "+l"(acc) : "l"(a), "l"(b));
}
__device__ __forceinline__ u64 pk(float lo, float hi) {
    u64 r; asm("mov.b64 %0, {%1, %2};" : "=l"(r) : "f"(lo), "f"(hi)); return r;
}
__device__ __forceinline__ void unpk(float& lo, float& hi, u64 v) {
    asm("mov.b64 {%0, %1}, %2;" : "=f"(lo), "=f"(hi) : "l"(v));
}
__device__ __forceinline__ float hadd(u64 v) {
    float a, b; unpk(a, b, v); return a + b;
}

// ---------------------------------------------------------------------------
// Kernel 1: gi = x @ W_ih^T + b_ih.  No k-split, no reduce pass.
// 64x64 tile, 128 threads (ty=tid>>3 [16] -> 4 m, tx=tid&7 [8] -> 8 n),
// m-paired FFMA2. Smem [k][m]/[k][n] transposed (static 35 KB),
// reg-prefetch double buffer. Grid 384 (~2.6 blocks/SM).
// ---------------------------------------------------------------------------
#define SG 68            // smem row stride ([k][64+pad]), 272B, 16B-aligned

__global__ void __launch_bounds__(128) gemm_gi_kernel(
    const float* __restrict__ A,        // x [2048][512]
    const float* __restrict__ B,        // W_ih [768][512]
    const float* __restrict__ bias)     // b_ih [768]
{
    __shared__ float As[2][32 * SG];    // 17408 B
    __shared__ float Bs[2][32 * SG];    // 17408 B

    const int tid = threadIdx.x;
    const int tx  = tid & 7;
    const int ty  = tid >> 3;
    const int n0  = blockIdx.x * 64;
    const int m0  = blockIdx.y * 64;

    float4 ra[4], rb[4];

    #define LDG_CHUNK(c) {                                                    \
        const int kb_ = (c) * 32;                                             \
        _Pragma("unroll")                                                     \
        for (int i_ = 0; i_ < 4; i_++) {                                      \
            int idx_ = tid + 128 * i_;                                        \
            int r_ = idx_ >> 3, c4_ = (idx_ & 7) * 4;                         \
            ra[i_] = *(const float4*)&A[(m0 + r_) * NINP + kb_ + c4_];        \
            rb[i_] = *(const float4*)&B[(n0 + r_) * NINP + kb_ + c4_];        \
        }                                                                     \
    }

    #define STS_CHUNK(buf) {                                                  \
        _Pragma("unroll")                                                     \
        for (int i_ = 0; i_ < 4; i_++) {                                      \
            int idx_ = tid + 128 * i_;                                        \
            int r_ = idx_ >> 3, kc_ = (idx_ & 7) * 4;                         \
            As[buf][(kc_ + 0) * SG + r_] = ra[i_].x;                          \
            As[buf][(kc_ + 1) * SG + r_] = ra[i_].y;                          \
            As[buf][(kc_ + 2) * SG + r_] = ra[i_].z;                          \
            As[buf][(kc_ + 3) * SG + r_] = ra[i_].w;                          \
            Bs[buf][(kc_ + 0) * SG + r_] = rb[i_].x;                          \
            Bs[buf][(kc_ + 1) * SG + r_] = rb[i_].y;                          \
            Bs[buf][(kc_ + 2) * SG + r_] = rb[i_].z;                          \
            Bs[buf][(kc_ + 3) * SG + r_] = rb[i_].w;                          \
        }                                                                     \
    }

    u64 acc[2][8];                      // 2 m-pairs x 8 n
#pragma unroll
    for (int i = 0; i < 2; i++)
#pragma unroll
        for (int j = 0; j < 8; j++) acc[i][j] = 0ull;

    LDG_CHUNK(0);
    STS_CHUNK(0);
    LDG_CHUNK(1);
    __syncthreads();

#pragma unroll 1
    for (int c = 0; c < 16; c++) {
        const int buf = c & 1;
        if (c < 15) STS_CHUNK(buf ^ 1);
        if (c < 14) LDG_CHUNK(c + 2);

        const float* Ab = As[buf];
        const float* Bb = Bs[buf];
#pragma unroll
        for (int k = 0; k < 32; k++) {
            ulonglong2 a2 = *(const ulonglong2*)(Ab + k * SG + ty * 4);
            float4 b1 = *(const float4*)(Bb + k * SG + tx * 4);
            float4 b2 = *(const float4*)(Bb + k * SG + 32 + tx * 4);
            u64 bb[8];
            bb[0] = pk(b1.x, b1.x); bb[1] = pk(b1.y, b1.y);
            bb[2] = pk(b1.z, b1.z); bb[3] = pk(b1.w, b1.w);
            bb[4] = pk(b2.x, b2.x); bb[5] = pk(b2.y, b2.y);
            bb[6] = pk(b2.z, b2.z); bb[7] = pk(b2.w, b2.w);
#pragma unroll
            for (int j = 0; j < 8; j++) {
                fma2(acc[0][j], a2.x, bb[j]);
                fma2(acc[1][j], a2.y, bb[j]);
            }
        }
        __syncthreads();
    }

    // epilogue: unpack m-pairs -> per-m rows, add bias, write g_gi
    float4 bj1 = *(const float4*)&bias[n0 + tx * 4];
    float4 bj2 = *(const float4*)&bias[n0 + 32 + tx * 4];
#pragma unroll
    for (int p = 0; p < 2; p++) {
        int mrow = m0 + ty * 4 + p * 2;
        float lo[8], hi[8];
#pragma unroll
        for (int j = 0; j < 8; j++) unpk(lo[j], hi[j], acc[p][j]);
        *(float4*)&g_gi[mrow * GI_COLS + n0 + tx * 4] =
            make_float4(lo[0] + bj1.x, lo[1] + bj1.y, lo[2] + bj1.z, lo[3] + bj1.w);
        *(float4*)&g_gi[mrow * GI_COLS + n0 + 32 + tx * 4] =
            make_float4(lo[4] + bj2.x, lo[5] + bj2.y, lo[6] + bj2.z, lo[7] + bj2.w);
        *(float4*)&g_gi[(mrow + 1) * GI_COLS + n0 + tx * 4] =
            make_float4(hi[0] + bj1.x, hi[1] + bj1.y, hi[2] + bj1.z, hi[3] + bj1.w);
        *(float4*)&g_gi[(mrow + 1) * GI_COLS + n0 + 32 + tx * 4] =
            make_float4(hi[4] + bj2.x, hi[5] + bj2.y, hi[6] + bj2.z, hi[7] + bj2.w);
    }
    #undef LDG_CHUNK
    #undef STS_CHUNK
}

// ---------------------------------------------------------------------------
// Kernel 1c: h_read per n (verified r11, unchanged)
// ---------------------------------------------------------------------------
__global__ void __launch_bounds__(256) hr_kernel(
    const float* __restrict__ h,
    const float* __restrict__ w_read)
{
    __shared__ float Wr[512];
    const int tid = threadIdx.x;
    if (tid < 128) ((float4*)Wr)[tid] = ((const float4*)w_read)[tid];
    __syncthreads();

    const int n = blockIdx.x * 256 + tid;
    float h2[32];
    {
        const float4* hp = (const float4*)(h + n * MM);
#pragma unroll
        for (int i = 0; i < 8; i++) {
            float4 v = hp[i];
            h2[4*i] = v.x; h2[4*i+1] = v.y; h2[4*i+2] = v.z; h2[4*i+3] = v.w;
        }
    }
    float hr[16];
#pragma unroll
    for (int f = 0; f < 16; f++) hr[f] = 0.f;
#pragma unroll 4
    for (int m = 0; m < 32; m++) {
        const float4* w = (const float4*)(Wr + m * 16);
        float hm = h2[m];
#pragma unroll
        for (int f4 = 0; f4 < 4; f4++) {
            float4 v = w[f4];
            hr[4*f4]   = fmaf(hm, v.x, hr[4*f4]);
            hr[4*f4+1] = fmaf(hm, v.y, hr[4*f4+1]);
            hr[4*f4+2] = fmaf(hm, v.z, hr[4*f4+2]);
            hr[4*f4+3] = fmaf(hm, v.w, hr[4*f4+3]);
        }
    }
    float4* d = (float4*)(g_hr + n * 16);
#pragma unroll
    for (int f4 = 0; f4 < 4; f4++)
        d[f4] = make_float4(hr[4*f4], hr[4*f4+1], hr[4*f4+2], hr[4*f4+3]);
}

// ---------------------------------------------------------------------------
// Kernel A: gates + hnext + logit (verified r11 paired version, unchanged)
// ---------------------------------------------------------------------------
#define PT 192
__global__ void __launch_bounds__(PT, 2) gates_kernel(
    const float* __restrict__ h,
    const float* __restrict__ W_hh,
    const float* __restrict__ b_hh,
    const float* __restrict__ w_write)
{
    __shared__ float Wg[96 * 32];
    __shared__ float Ww[32 * 16];
    __shared__ float bs[96];

    const int tid = threadIdx.x;
    const int t   = blockIdx.y;

    {
        const float4* s1 = (const float4*)(W_hh + t * 96 * 32);
        float4* d1 = (float4*)Wg;
        for (int i = tid; i < 768; i += PT) d1[i] = s1[i];
        if (tid < 128) ((float4*)Ww)[tid] = ((const float4*)(w_write + t * 512))[tid];
        if (tid < 24)  ((float4*)bs)[tid] = ((const float4*)(b_hh + t * 96))[tid];
    }
    __syncthreads();

    const int p = blockIdx.x * PT + tid;
    if (p >= NPAIR) return;
    const int b  = p >> 3;
    const int n1 = b * 16 + (p & 7);
    const int n2 = n1 + 8;

    u64 hA[16], hB[16];
    {
        const ulonglong2* h1 = (const ulonglong2*)(h + n1 * MM);
        const ulonglong2* h2 = (const ulonglong2*)(h + n2 * MM);
#pragma unroll
        for (int q = 0; q < 8; q++) {
            ulonglong2 v = h1[q]; hA[2*q] = v.x; hA[2*q+1] = v.y;
            ulonglong2 w = h2[q]; hB[2*q] = w.x; hB[2*q+1] = w.y;
        }
    }

    u64 hrA[8], hrB[8];
    {
        const float4* r1 = (const float4*)(g_hr + n1 * 16);
        const float4* r2 = (const float4*)(g_hr + n2 * 16);
#pragma unroll
        for (int q = 0; q < 4; q++) {
            float4 v = r1[q];
            hrA[2*q]   = pk(v.x, v.y);
            hrA[2*q+1] = pk(v.z, v.w);
            float4 w = r2[q];
            hrB[2*q]   = pk(w.x, w.y);
            hrB[2*q+1] = pk(w.z, w.w);
        }
    }

    const float* gib = g_gi + b * GI_COLS + t * 96;
    float* ho1 = g_hn + (t * (size_t)NTOT + n1) * MM;
    float* ho2 = g_hn + (t * (size_t)NTOT + n2) * MM;
    float lg1 = 0.f, lg2 = 0.f;

#pragma unroll 1
    for (int l4 = 0; l4 < 8; l4++) {
        float Ga[4], Gb[4], Gc[4];
        *(float4*)Ga = *(const float4*)(gib + 4*l4);
        *(float4*)Gb = *(const float4*)(gib + 32 + 4*l4);
        *(float4*)Gc = *(const float4*)(gib + 64 + 4*l4);
        float o1[4], o2[4];
#pragma unroll
        for (int li = 0; li < 4; li++) {
            const int l = 4*l4 + li;
            const ulonglong2* wr = (const ulonglong2*)(Wg + l * 32);
            const ulonglong2* wz = (const ulonglong2*)(Wg + (32 + l) * 32);
            const ulonglong2* wn = (const ulonglong2*)(Wg + (64 + l) * 32);
            u64 aR1 = pk(bs[l],      0.f), aR2 = aR1;
            u64 aZ1 = pk(bs[32 + l], 0.f), aZ2 = aZ1;
            u64 aN1 = pk(bs[64 + l], 0.f), aN2 = aN1;
#pragma unroll
            for (int q = 0; q < 8; q++) {
                ulonglong2 wa = wr[q];
                fma2(aR1, wa.x, hA[2*q]); fma2(aR1, wa.y, hA[2*q+1]);
                fma2(aR2, wa.x, hB[2*q]); fma2(aR2, wa.y, hB[2*q+1]);
            }
#pragma unroll
            for (int q = 0; q < 8; q++) {
                ulonglong2 wb = wz[q];
                fma2(aZ1, wb.x, hA[2*q]); fma2(aZ1, wb.y, hA[2*q+1]);
                fma2(aZ2, wb.x, hB[2*q]); fma2(aZ2, wb.y, hB[2*q+1]);
            }
#pragma unroll
            for (int q = 0; q < 8; q++) {
                ulonglong2 wc = wn[q];
                fma2(aN1, wc.x, hA[2*q]); fma2(aN1, wc.y, hA[2*q+1]);
                fma2(aN2, wc.x, hB[2*q]); fma2(aN2, wc.y, hB[2*q+1]);
            }
            const ulonglong2* ww = (const ulonglong2*)(Ww + l * 16);
            ulonglong2 w0 = ww[0], w1 = ww[1], w2 = ww[2], w3 = ww[3];
            u64 aA1 = 0ull, aA2 = 0ull;
            fma2(aA1, w0.x, hrA[0]); fma2(aA1, w0.y, hrA[1]);
            fma2(aA1, w1.x, hrA[2]); fma2(aA1, w1.y, hrA[3]);
            fma2(aA1, w2.x, hrA[4]); fma2(aA1, w2.y, hrA[5]);
            fma2(aA1, w3.x, hrA[6]); fma2(aA1, w3.y, hrA[7]);
            fma2(aA2, w0.x, hrB[0]); fma2(aA2, w0.y, hrB[1]);
            fma2(aA2, w1.x, hrB[2]); fma2(aA2, w1.y, hrB[3]);
            fma2(aA2, w2.x, hrB[4]); fma2(aA2, w2.y, hrB[5]);
            fma2(aA2, w3.x, hrB[6]); fma2(aA2, w3.y, hrB[7]);

            {
                float ar = hadd(aR1), az = hadd(aZ1), an = hadd(aN1), av = hadd(aA1);
                float lo, hi; unpk(lo, hi, hA[l >> 1]); float hl = (l & 1) ? hi : lo;
                float r  = __fdividef(1.f, 1.f + __expf(-(Ga[li] + ar)));
                float z  = __fdividef(1.f, 1.f + __expf(-(Gb[li] + az)));
                float xn = Gc[li] + r * an;
                float e2 = __expf(-2.f * xn);
                float nn = __fdividef(1.f - e2, 1.f + e2);
                float hn = (1.f - z) * nn + z * hl;
                o1[li] = hn;
                lg1 = fmaf(hn, av, lg1);
            }
            {
                float ar = hadd(aR2), az = hadd(aZ2), an = hadd(aN2), av = hadd(aA2);
                float lo, hi; unpk(lo, hi, hB[l >> 1]); float hl = (l & 1) ? hi : lo;
                float r  = __fdividef(1.f, 1.f + __expf(-(Ga[li] + ar)));
                float z  = __fdividef(1.f, 1.f + __expf(-(Gb[li] + az)));
                float xn = Gc[li] + r * an;
                float e2 = __expf(-2.f * xn);
                float nn = __fdividef(1.f - e2, 1.f + e2);
                float hn = (1.f - z) * nn + z * hl;
                o2[li] = hn;
                lg2 = fmaf(hn, av, lg2);
            }
        }
        *(float4*)(ho1 + 4*l4) = *(float4*)o1;
        *(float4*)(ho2 + 4*l4) = *(float4*)o2;
    }
    g_lg[n1 * TT + t] = lg1;
    g_lg[n2 * TT + t] = lg2;
}

// ---------------------------------------------------------------------------
// Kernel B: gumbel softmax + hard select + gather + outputs (unchanged)
// ---------------------------------------------------------------------------
__global__ void __launch_bounds__(256) select_kernel(
    const float* __restrict__ gum,
    float* __restrict__ out)
{
    const int n = blockIdx.x * 256 + threadIdx.x;

    float s[8];
    {
        const float4* lp = (const float4*)(g_lg + n * TT);
        const float4* gp = (const float4*)(gum + n * TT);
        float4 l0 = lp[0], l1 = lp[1], g0 = gp[0], g1 = gp[1];
        s[0] = (l0.x + g0.x) * 2.f; s[1] = (l0.y + g0.y) * 2.f;
        s[2] = (l0.z + g0.z) * 2.f; s[3] = (l0.w + g0.w) * 2.f;
        s[4] = (l1.x + g1.x) * 2.f; s[5] = (l1.y + g1.y) * 2.f;
        s[6] = (l1.z + g1.z) * 2.f; s[7] = (l1.w + g1.w) * 2.f;
    }
    float smax = s[0];
    int amax = 0;
#pragma unroll
    for (int t = 1; t < 8; t++)
        if (s[t] > smax) { smax = s[t]; amax = t; }
    float sum = 0.f;
#pragma unroll
    for (int t = 0; t < 8; t++) sum += __expf(s[t] - smax);

    float p = __fdividef(1.f, sum);
    float attv = (1.f + p) - p;

    const float4* hp = (const float4*)(g_hn + (amax * (size_t)NTOT + n) * MM);
    float4* ho = (float4*)(out + n * MM);
#pragma unroll
    for (int i = 0; i < 8; i++) {
        float4 v = hp[i];
        v.x *= attv; v.y *= attv; v.z *= attv; v.w *= attv;
        ho[i] = v;
    }
    float* ao = out + BS * NHID + n * TT;
#pragma unroll
    for (int t = 0; t < 8; t++) ao[t] = (t == amax) ? attv : 0.f;
}

// ---------------------------------------------------------------------------
extern "C" void kernel_launch(void* const* d_in, const int* in_sizes, int n_in,
                              void* d_out, int out_size)
{
    const float* x       = (const float*)d_in[0];
    const float* h       = (const float*)d_in[1];
    const float* W_ih    = (const float*)d_in[2];
    const float* W_hh    = (const float*)d_in[3];
    const float* b_ih    = (const float*)d_in[4];
    const float* b_hh    = (const float*)d_in[5];
    const float* w_read  = (const float*)d_in[6];
    const float* w_write = (const float*)d_in[7];
    const float* gum     = (const float*)d_in[8];
    float* out = (float*)d_out;

    // gi GEMM: single pass, fma2, bias fused
    dim3 g1(GI_COLS / 64, BS / 64);                   // (12, 32) = 384
    gemm_gi_kernel<<<g1, 128>>>(x, W_ih, b_ih);

    // h_read precompute
    hr_kernel<<<NTOT / 256, 256>>>(h, w_read);

    dim3 g2((NPAIR + PT - 1) / PT, TT);               // (86, 8)
    gates_kernel<<<g2, PT>>>(h, W_hh, b_hh, w_write);

    select_kernel<<<NTOT / 256, 256>>>(gum, out);
}